// round 16
// baseline (speedup 1.0000x reference)
#include <cuda_runtime.h>
#include <cuda_fp16.h>
#include <cstdint>

#define NB 2
#define SEQ 4096
#define DMODEL 512
#define NH 8
#define HD 64
#define MTOT (NB*SEQ)      // 8192
#define BHT (NB*NH)        // 16

// Scratch (static device globals; no runtime allocation allowed)
__device__ __half x_h[(size_t)MTOT * DMODEL];
__device__ __half Wqkv_h[(size_t)3 * DMODEL * DMODEL];
__device__ __half Wo_h[(size_t)DMODEL * DMODEL];
__device__ __half g_qh[(size_t)BHT * SEQ * HD];
__device__ __half g_kh[(size_t)BHT * SEQ * HD];
__device__ __half g_vh[(size_t)BHT * SEQ * HD];
__device__ __half g_yh[(size_t)MTOT * DMODEL];

// ---------------------------------------------------------------------------
// Helpers
// ---------------------------------------------------------------------------
__device__ __forceinline__ uint32_t ex2_h2(uint32_t x) {   // 2 exps / MUFU op
    uint32_t y;
    asm("ex2.approx.f16x2 %0, %1;" : "=r"(y) : "r"(x));
    return y;
}
__device__ __forceinline__ void mma_h(float4& d,
                                      uint32_t a0, uint32_t a1, uint32_t a2, uint32_t a3,
                                      uint32_t b0, uint32_t b1) {
    asm("mma.sync.aligned.m16n8k16.row.col.f32.f16.f16.f32 "
        "{%0,%1,%2,%3},{%4,%5,%6,%7},{%8,%9},{%0,%1,%2,%3};"
        : "+f"(d.x), "+f"(d.y), "+f"(d.z), "+f"(d.w)
        : "r"(a0), "r"(a1), "r"(a2), "r"(a3), "r"(b0), "r"(b1));
}
// VOLATILE + memory clobber: ldmatrix must not be hoisted above cp.async
// waits / __syncthreads, nor CSE'd across ring iterations.
__device__ __forceinline__ void ldsm_x4(uint32_t& r0, uint32_t& r1,
                                        uint32_t& r2, uint32_t& r3, uint32_t addr) {
    asm volatile("ldmatrix.sync.aligned.m8n8.x4.shared.b16 {%0,%1,%2,%3}, [%4];"
        : "=r"(r0), "=r"(r1), "=r"(r2), "=r"(r3) : "r"(addr) : "memory");
}
__device__ __forceinline__ void ldsm_x4_trans(uint32_t& r0, uint32_t& r1,
                                              uint32_t& r2, uint32_t& r3, uint32_t addr) {
    asm volatile("ldmatrix.sync.aligned.m8n8.x4.trans.shared.b16 {%0,%1,%2,%3}, [%4];"
        : "=r"(r0), "=r"(r1), "=r"(r2), "=r"(r3) : "r"(addr) : "memory");
}
__device__ __forceinline__ uint32_t h2u(__half2 h) {
    union { __half2 h; uint32_t u; } c; c.h = h; return c.u;
}
__device__ __forceinline__ void cp16(uint32_t dst, const void* src) {
    asm volatile("cp.async.ca.shared.global [%0], [%1], 16;" :: "r"(dst), "l"(src));
}
#define CP_COMMIT() asm volatile("cp.async.commit_group;" ::: "memory")
#define CP_WAIT1()  asm volatile("cp.async.wait_group 1;" ::: "memory")
#define CP_WAIT0()  asm volatile("cp.async.wait_group 0;" ::: "memory")

// ---------------------------------------------------------------------------
// f32 -> f16 conversion: ONE launch for all three inputs
// ---------------------------------------------------------------------------
#define NX (MTOT * DMODEL)              // 4,194,304
#define NQ (3 * DMODEL * DMODEL)        // 786,432
#define NW (DMODEL * DMODEL)            // 262,144

__global__ void f2h_all(const float* __restrict__ x,
                        const float* __restrict__ wq,
                        const float* __restrict__ wo) {
    int i = (blockIdx.x * blockDim.x + threadIdx.x) * 4;
    const float* src;
    __half* dst;
    int base;
    if (i < NX)           { src = x;  dst = x_h;    base = i; }
    else if (i < NX + NQ) { src = wq; dst = Wqkv_h; base = i - NX; }
    else if (i < NX + NQ + NW) { src = wo; dst = Wo_h; base = i - NX - NQ; }
    else return;
    float4 v = *(const float4*)(src + base);
    uint2 u = {h2u(__floats2half2_rn(v.x, v.y)), h2u(__floats2half2_rn(v.z, v.w))};
    *(uint2*)(dst + base) = u;
}

// ---------------------------------------------------------------------------
// fp16 GEMM: C[m,n] = sum_k A[m,k]*W[n,k] + bias[n]
// Tile 128(M) x 64(N), 8 warps = 4M x 2N, warp 32x32.
// K chunks of 64 halves, 2-stage cp.async ring, one barrier per chunk.
// Dynamic smem 55.3 KB, 3 CTAs/SM.
// MODE 0: A = x_h, W = Wqkv_h, scatter to g_qh/g_kh/g_vh (half, [bh][s][hd])
// MODE 1: A = g_yh, W = Wo_h, write f32 out
// ---------------------------------------------------------------------------
#define GLD 36                               // u32 row stride (144 B)
#define GA_U32 (128 * GLD)                   // A per stage
#define GB_U32 (64 * GLD)                    // B per stage
#define GSTG_BYTES ((GA_U32 + GB_U32) * 4)   // 27,648 B
#define GEMM_DSM (2 * GSTG_BYTES)            // 55,296 B

template<int MODE>
__global__ __launch_bounds__(256, 3) void gemm_h(const float* __restrict__ bias,
                                                 float* __restrict__ Cout,
                                                 int K, int N)
{
    extern __shared__ uint32_t gsm[];
    const uint32_t smb = (uint32_t)__cvta_generic_to_shared(gsm);

    const int tid = threadIdx.x, wid = tid >> 5, lane = tid & 31;
    const int g = lane >> 2, t = lane & 3;
    const int wm = wid & 3, wn = wid >> 2;
    const int m0 = blockIdx.x * 128, n0 = blockIdx.y * 64;

    const __half* __restrict__ Ap = (MODE == 1) ? g_yh : x_h;
    const __half* __restrict__ Wp = (MODE == 1) ? Wo_h : Wqkv_h;

    // ldmatrix lane offsets (bytes), row stride 144B
    const uint32_t aOff = (wm * 32 + (lane & 15)) * 144 + (lane >> 4) * 16;
    const uint32_t bOff = (wn * 32 + ((lane >> 4) & 1) * 8 + (lane & 7)) * 144
                        + ((lane >> 3) & 1) * 16;

    float4 acc[2][4];
#pragma unroll
    for (int mt = 0; mt < 2; mt++)
#pragma unroll
        for (int j = 0; j < 4; j++) acc[mt][j] = make_float4(0.f, 0.f, 0.f, 0.f);

    const int nchunks = K / 64;   // 8
    auto issue = [&](int c, int s) {
        uint32_t base = smb + (uint32_t)s * GSTG_BYTES;
#pragma unroll
        for (int it = 0; it < 4; it++) {
            int idx = tid + it * 256, row = idx >> 3, q = idx & 7;
            cp16(base + (uint32_t)(row * GLD + q * 4) * 4,
                 Ap + (size_t)(m0 + row) * K + c * 64 + q * 8);
        }
#pragma unroll
        for (int it = 0; it < 2; it++) {
            int idx = tid + it * 256, row = idx >> 3, q = idx & 7;
            cp16(base + (uint32_t)GA_U32 * 4 + (uint32_t)(row * GLD + q * 4) * 4,
                 Wp + (size_t)(n0 + row) * K + c * 64 + q * 8);
        }
        CP_COMMIT();
    };

    issue(0, 0);
    for (int c = 0; c < nchunks; c++) {
        const int s = c & 1;
        CP_WAIT0();
        __syncthreads();
        if (c + 1 < nchunks) issue(c + 1, s ^ 1);

        const uint32_t aB = smb + (uint32_t)s * GSTG_BYTES + aOff;
        const uint32_t bB = smb + (uint32_t)s * GSTG_BYTES + (uint32_t)GA_U32 * 4 + bOff;
#pragma unroll
        for (int kc = 0; kc < 4; kc++) {
            uint32_t a[2][4], bf[4][2];
            ldsm_x4(a[0][0], a[0][1], a[0][2], a[0][3], aB + kc * 32);
            ldsm_x4(a[1][0], a[1][1], a[1][2], a[1][3], aB + 16 * 144 + kc * 32);
            ldsm_x4(bf[0][0], bf[0][1], bf[1][0], bf[1][1], bB + kc * 32);
            ldsm_x4(bf[2][0], bf[2][1], bf[3][0], bf[3][1], bB + 16 * 144 + kc * 32);
#pragma unroll
            for (int mt = 0; mt < 2; mt++)
#pragma unroll
                for (int j = 0; j < 4; j++)
                    mma_h(acc[mt][j], a[mt][0], a[mt][1], a[mt][2], a[mt][3],
                          bf[j][0], bf[j][1]);
        }
    }

    // Epilogue (64-wide n tile = exactly one head for MODE 0)
#pragma unroll
    for (int j = 0; j < 4; j++) {
        int n = n0 + wn * 32 + j * 8 + 2 * t;
        float2 bb = *(const float2*)&bias[n];
#pragma unroll
        for (int mt = 0; mt < 2; mt++) {
            int ma = m0 + wm * 32 + mt * 16 + g;
            float x0 = acc[mt][j].x + bb.x, y0 = acc[mt][j].y + bb.y;
            float x1 = acc[mt][j].z + bb.x, y1 = acc[mt][j].w + bb.y;
            if (MODE == 0) {
                int sel = n0 >> 9, h = (n0 & 511) >> 6, hd0 = n & 63;
                __half* __restrict__ dst = (sel == 0) ? g_qh : ((sel == 1) ? g_kh : g_vh);
                int bh = (ma >> 12) * NH + h, s = ma & 4095;
                size_t base = ((size_t)bh * SEQ + s) * HD + hd0;
                *(uint32_t*)&dst[base] = h2u(__floats2half2_rn(x0, y0));
                *(uint32_t*)&dst[base + (size_t)8 * HD] = h2u(__floats2half2_rn(x1, y1));
            } else {
                *(float2*)&Cout[(size_t)ma * N + n] = make_float2(x0, y0);
                *(float2*)&Cout[(size_t)(ma + 8) * N + n] = make_float2(x1, y1);
            }
        }
    }
}

// ---------------------------------------------------------------------------
// Flash attention, fp16 mma.sync, causal, no-max softmax.
// Q tile 128 rows, 256 thr / 8 warps (warp w owns rows w*16..+15, per-warp
// code identical to R14) -> each K/V tile feeds 8 warps instead of 4:
// L2->SMEM K/V traffic HALVES (532 MB -> 266 MB), tile-iters & barriers halve.
// 2 CTAs/SM. f16x2 exp, l-via-ones-MMA, V-frag pipeline, warp causal skip.
// 3-stage cp.async K/V ring, one __syncthreads per k-tile.
// ---------------------------------------------------------------------------
#define SKV 36
#define KV_STG (2 * 64 * SKV)             // u32 per stage (K then V)
#define ATTN_DSM (3 * KV_STG * 4)         // 55,296 bytes

__global__ __launch_bounds__(256, 2) void attn_h()
{
    extern __shared__ uint32_t sm[];

    const int qt = (int)gridDim.x - 1 - (int)blockIdx.x;   // heavy blocks first
    const int bh = blockIdx.y;
    const int tid = threadIdx.x, wid = tid >> 5, lane = tid & 31;
    const int g = lane >> 2, t = lane & 3;
    const int q0 = qt * 128;
    const int rw = q0 + wid * 16;          // warp's first q row
    const int r0 = rw + g;

    const __half* __restrict__ qb = g_qh + (size_t)bh * SEQ * HD;
    const __half* __restrict__ kb = g_kh + (size_t)bh * SEQ * HD;
    const __half* __restrict__ vb = g_vh + (size_t)bh * SEQ * HD;

    const uint32_t smb = (uint32_t)__cvta_generic_to_shared(sm);

    // cp.async staging: K,V each 512 uint4 over 256 thr = 2 each
    const uint32_t vbase_u32 = (uint32_t)(64 * SKV);
    auto issue_kv = [&](int kt, int s) {
        uint32_t sb = smb + (uint32_t)s * (KV_STG * 4);
#pragma unroll
        for (int it = 0; it < 2; it++) {
            int idx = tid + it * 256, row = idx >> 3, q = idx & 7;
            const __half* ksrc = kb + (size_t)(kt * 64 + row) * HD + q * 8;
            const __half* vsrc = vb + (size_t)(kt * 64 + row) * HD + q * 8;
            cp16(sb + (uint32_t)(row * SKV + q * 4) * 4, ksrc);
            cp16(sb + (vbase_u32 + (uint32_t)(row * SKV + q * 4)) * 4, vsrc);
        }
        CP_COMMIT();
    };

    // Q fragments in registers (constant over mainloop)
    uint32_t qf[4][4];
#pragma unroll
    for (int kc = 0; kc < 4; kc++) {
        qf[kc][0] = *(const uint32_t*)(qb + (size_t)r0 * HD + kc * 16 + 2 * t);
        qf[kc][1] = *(const uint32_t*)(qb + (size_t)(r0 + 8) * HD + kc * 16 + 2 * t);
        qf[kc][2] = *(const uint32_t*)(qb + (size_t)r0 * HD + kc * 16 + 8 + 2 * t);
        qf[kc][3] = *(const uint32_t*)(qb + (size_t)(r0 + 8) * HD + kc * 16 + 8 + 2 * t);
    }

    float4 o[8];
#pragma unroll
    for (int j = 0; j < 8; j++) o[j] = make_float4(0.f, 0.f, 0.f, 0.f);
    float4 lacc = make_float4(0.f, 0.f, 0.f, 0.f);   // l in .x (row g), .z (row g+8)
    const uint32_t ones_b = (g == 0) ? 0x3C003C00u : 0u;   // B[:,0]=1 fragment

    // ldmatrix lane offsets (bytes within a stage)
    const uint32_t kfOff = (((lane >> 4) << 3) + (lane & 7)) * (SKV * 4)
                         + ((lane >> 3) & 1) * 16;
    const uint32_t vfOff = vbase_u32 * 4
                         + (lane & 15) * (SKV * 4) + ((lane >> 4) & 1) * 16;

    const int kt_end = 2 * qt + 1;
    issue_kv(0, 0);
    issue_kv(1, 1);
    for (int kt = 0; kt <= kt_end; kt++) {
        const int s = kt % 3;
        if (kt < kt_end) CP_WAIT1();
        else             CP_WAIT0();
        __syncthreads();
        if (kt + 2 <= kt_end) issue_kv(kt + 2, (kt + 2) % 3);

        if (kt * 64 <= rw + 15) {          // warp-level causal skip
            const uint32_t stg = smb + (uint32_t)s * (KV_STG * 4);
            const uint32_t kfBase = stg + kfOff;
            const uint32_t vfBase = stg + vfOff;

            // ---- preload V frags for kc=0 (independent of softmax) ----
            uint32_t vbuf[2][16];
#pragma unroll
            for (int jp = 0; jp < 4; jp++)
                ldsm_x4_trans(vbuf[0][4 * jp], vbuf[0][4 * jp + 1],
                              vbuf[0][4 * jp + 2], vbuf[0][4 * jp + 3],
                              vfBase + jp * 32);

            // ---- S = Q K^T (ldmatrix.x4 K frags) ----
            float4 sc[8];
#pragma unroll
            for (int j = 0; j < 8; j++) sc[j] = make_float4(0.f, 0.f, 0.f, 0.f);
#pragma unroll
            for (int kc = 0; kc < 4; kc++) {
                uint32_t base = kfBase + kc * 32;
#pragma unroll
                for (int jp = 0; jp < 4; jp++) {
                    uint32_t b0, b1, b2, b3;
                    ldsm_x4(b0, b1, b2, b3, base + jp * 16 * (SKV * 4));
                    mma_h(sc[2 * jp],     qf[kc][0], qf[kc][1], qf[kc][2], qf[kc][3], b0, b1);
                    mma_h(sc[2 * jp + 1], qf[kc][0], qf[kc][1], qf[kc][2], qf[kc][3], b2, b3);
                }
            }

            // ---- p = exp2(s*SC) in f16x2; mask only near the diagonal ----
            const float SC = 0.18033688f;   // 0.125 * log2(e)
            uint32_t pf[8][2];
            if (kt * 64 + 63 > rw) {        // warp-uniform mask branch
#pragma unroll
                for (int j = 0; j < 8; j++) {
                    int c = kt * 64 + j * 8 + 2 * t;
                    float vx = (c     > r0)     ? -64.f : sc[j].x * SC;
                    float vy = (c + 1 > r0)     ? -64.f : sc[j].y * SC;
                    float vz = (c     > r0 + 8) ? -64.f : sc[j].z * SC;
                    float vw = (c + 1 > r0 + 8) ? -64.f : sc[j].w * SC;
                    pf[j][0] = ex2_h2(h2u(__floats2half2_rn(vx, vy)));
                    pf[j][1] = ex2_h2(h2u(__floats2half2_rn(vz, vw)));
                }
            } else {
#pragma unroll
                for (int j = 0; j < 8; j++) {
                    pf[j][0] = ex2_h2(h2u(__floats2half2_rn(sc[j].x * SC, sc[j].y * SC)));
                    pf[j][1] = ex2_h2(h2u(__floats2half2_rn(sc[j].z * SC, sc[j].w * SC)));
                }
            }

            // ---- O += P V ; l += P @ ones  (V-frag prefetch pipeline) ----
#pragma unroll
            for (int kc = 0; kc < 4; kc++) {
                if (kc < 3) {
                    uint32_t nrow = vfBase + (uint32_t)(16 * (kc + 1)) * (SKV * 4);
#pragma unroll
                    for (int jp = 0; jp < 4; jp++)
                        ldsm_x4_trans(vbuf[(kc + 1) & 1][4 * jp], vbuf[(kc + 1) & 1][4 * jp + 1],
                                      vbuf[(kc + 1) & 1][4 * jp + 2], vbuf[(kc + 1) & 1][4 * jp + 3],
                                      nrow + jp * 32);
                }
                uint32_t a0 = pf[2 * kc][0], a1 = pf[2 * kc][1];
                uint32_t a2 = pf[2 * kc + 1][0], a3 = pf[2 * kc + 1][1];
                mma_h(lacc, a0, a1, a2, a3, ones_b, ones_b);   // row-sum on tensor pipe
#pragma unroll
                for (int jp = 0; jp < 4; jp++) {
                    mma_h(o[2 * jp],     a0, a1, a2, a3,
                          vbuf[kc & 1][4 * jp], vbuf[kc & 1][4 * jp + 1]);
                    mma_h(o[2 * jp + 1], a0, a1, a2, a3,
                          vbuf[kc & 1][4 * jp + 2], vbuf[kc & 1][4 * jp + 3]);
                }
            }
        }
    }

    // l lives in column 0 of lacc -> held by the t=0 lane of each quad
    const float l0 = __shfl_sync(0xffffffffu, lacc.x, lane & ~3);
    const float l1 = __shfl_sync(0xffffffffu, lacc.z, lane & ~3);

    // Write y as half [b][s][h*64+hd]
    const int b = bh >> 3, h = bh & 7;
    const float inv0 = 1.0f / l0, inv1 = 1.0f / l1;
    size_t base0 = ((size_t)b * SEQ + r0) * DMODEL + h * HD;
#pragma unroll
    for (int j = 0; j < 8; j++) {
        *(uint32_t*)&g_yh[base0 + j * 8 + 2 * t] =
            h2u(__floats2half2_rn(o[j].x * inv0, o[j].y * inv0));
        *(uint32_t*)&g_yh[base0 + (size_t)8 * DMODEL + j * 8 + 2 * t] =
            h2u(__floats2half2_rn(o[j].z * inv1, o[j].w * inv1));
    }
}

// ---------------------------------------------------------------------------
extern "C" void kernel_launch(void* const* d_in, const int* in_sizes, int n_in,
                              void* d_out, int out_size)
{
    const float* x    = (const float*)d_in[0];
    const float* Wqkv = (const float*)d_in[1];
    const float* bqkv = (const float*)d_in[2];
    const float* Wo   = (const float*)d_in[3];
    const float* bo   = (const float*)d_in[4];
    float* out = (float*)d_out;

    cudaFuncSetAttribute(gemm_h<0>,
                         cudaFuncAttributeMaxDynamicSharedMemorySize, GEMM_DSM);
    cudaFuncSetAttribute(gemm_h<1>,
                         cudaFuncAttributeMaxDynamicSharedMemorySize, GEMM_DSM);
    cudaFuncSetAttribute(attn_h,
                         cudaFuncAttributeMaxDynamicSharedMemorySize, ATTN_DSM);

    // 0) f32 -> f16 pre-conversion (single launch for x, Wqkv, Wo)
    f2h_all<<<((NX + NQ + NW) / 4 + 255) / 256, 256>>>(x, Wqkv, Wo);

    // 1) QKV projection (fp16 HMMA, chunk-64 2-stage ring)
    gemm_h<0><<<dim3(MTOT / 128, (3 * DMODEL) / 64), 256, GEMM_DSM>>>(
        bqkv, nullptr, DMODEL, 3 * DMODEL);

    // 2) Causal flash attention (fp16 HMMA, Q-tile 128, halved K/V traffic)
    attn_h<<<dim3(SEQ / 128, BHT), 256, ATTN_DSM>>>();

    // 3) Output projection (fp16 HMMA)
    gemm_h<1><<<dim3(MTOT / 128, DMODEL / 64), 256, GEMM_DSM>>>(
        bo, out, DMODEL, DMODEL);
}

// round 17
// speedup vs baseline: 1.1456x; 1.1456x over previous
#include <cuda_runtime.h>
#include <cuda_fp16.h>
#include <cstdint>

#define NB 2
#define SEQ 4096
#define DMODEL 512
#define NH 8
#define HD 64
#define MTOT (NB*SEQ)      // 8192
#define BHT (NB*NH)        // 16

// Scratch (static device globals; no runtime allocation allowed)
__device__ __half x_h[(size_t)MTOT * DMODEL];
__device__ __half Wqkv_h[(size_t)3 * DMODEL * DMODEL];
__device__ __half Wo_h[(size_t)DMODEL * DMODEL];
__device__ __half g_qh[(size_t)BHT * SEQ * HD];
__device__ __half g_kh[(size_t)BHT * SEQ * HD];
__device__ __half g_vh[(size_t)BHT * SEQ * HD];
__device__ __half g_yh[(size_t)MTOT * DMODEL];

// ---------------------------------------------------------------------------
// Helpers
// ---------------------------------------------------------------------------
__device__ __forceinline__ uint32_t ex2_h2(uint32_t x) {   // 2 exps / MUFU op
    uint32_t y;
    asm("ex2.approx.f16x2 %0, %1;" : "=r"(y) : "r"(x));
    return y;
}
__device__ __forceinline__ void mma_h(float4& d,
                                      uint32_t a0, uint32_t a1, uint32_t a2, uint32_t a3,
                                      uint32_t b0, uint32_t b1) {
    asm("mma.sync.aligned.m16n8k16.row.col.f32.f16.f16.f32 "
        "{%0,%1,%2,%3},{%4,%5,%6,%7},{%8,%9},{%0,%1,%2,%3};"
        : "+f"(d.x), "+f"(d.y), "+f"(d.z), "+f"(d.w)
        : "r"(a0), "r"(a1), "r"(a2), "r"(a3), "r"(b0), "r"(b1));
}
// VOLATILE + memory clobber: ldmatrix must not be hoisted above cp.async
// waits / __syncthreads, nor CSE'd across ring iterations.
__device__ __forceinline__ void ldsm_x4(uint32_t& r0, uint32_t& r1,
                                        uint32_t& r2, uint32_t& r3, uint32_t addr) {
    asm volatile("ldmatrix.sync.aligned.m8n8.x4.shared.b16 {%0,%1,%2,%3}, [%4];"
        : "=r"(r0), "=r"(r1), "=r"(r2), "=r"(r3) : "r"(addr) : "memory");
}
__device__ __forceinline__ void ldsm_x4_trans(uint32_t& r0, uint32_t& r1,
                                              uint32_t& r2, uint32_t& r3, uint32_t addr) {
    asm volatile("ldmatrix.sync.aligned.m8n8.x4.trans.shared.b16 {%0,%1,%2,%3}, [%4];"
        : "=r"(r0), "=r"(r1), "=r"(r2), "=r"(r3) : "r"(addr) : "memory");
}
__device__ __forceinline__ uint32_t h2u(__half2 h) {
    union { __half2 h; uint32_t u; } c; c.h = h; return c.u;
}
__device__ __forceinline__ void cp16(uint32_t dst, const void* src) {
    asm volatile("cp.async.ca.shared.global [%0], [%1], 16;" :: "r"(dst), "l"(src));
}
#define CP_COMMIT() asm volatile("cp.async.commit_group;" ::: "memory")
#define CP_WAIT1()  asm volatile("cp.async.wait_group 1;" ::: "memory")
#define CP_WAIT0()  asm volatile("cp.async.wait_group 0;" ::: "memory")

// ---------------------------------------------------------------------------
// f32 -> f16 conversion: ONE launch for all three inputs
// ---------------------------------------------------------------------------
#define NX (MTOT * DMODEL)              // 4,194,304
#define NQ (3 * DMODEL * DMODEL)        // 786,432
#define NW (DMODEL * DMODEL)            // 262,144

__global__ void f2h_all(const float* __restrict__ x,
                        const float* __restrict__ wq,
                        const float* __restrict__ wo) {
    int i = (blockIdx.x * blockDim.x + threadIdx.x) * 4;
    const float* src;
    __half* dst;
    int base;
    if (i < NX)           { src = x;  dst = x_h;    base = i; }
    else if (i < NX + NQ) { src = wq; dst = Wqkv_h; base = i - NX; }
    else if (i < NX + NQ + NW) { src = wo; dst = Wo_h; base = i - NX - NQ; }
    else return;
    float4 v = *(const float4*)(src + base);
    uint2 u = {h2u(__floats2half2_rn(v.x, v.y)), h2u(__floats2half2_rn(v.z, v.w))};
    *(uint2*)(dst + base) = u;
}

// ---------------------------------------------------------------------------
// fp16 GEMM: C[m,n] = sum_k A[m,k]*W[n,k] + bias[n]
// NEW (R17): tile 128(M) x 128(N) -> L2 traffic -33%, mma/ldsm ratio +33%.
// 8 warps = 2M x 4N, warp 64x32. K chunks of 64 halves, 2-stage cp.async
// ring, one barrier per chunk. Dynamic smem 73.7 KB, 2 CTAs/SM.
// MODE 0: A = x_h, W = Wqkv_h, scatter to g_qh/g_kh/g_vh (half, [bh][s][hd])
// MODE 1: A = g_yh, W = Wo_h, write f32 out
// ---------------------------------------------------------------------------
#define GLD 36                               // u32 row stride (144 B)
#define GA_U32 (128 * GLD)                   // A per stage
#define GB_U32 (128 * GLD)                   // B per stage
#define GSTG_BYTES ((GA_U32 + GB_U32) * 4)   // 36,864 B
#define GEMM_DSM (2 * GSTG_BYTES)            // 73,728 B

template<int MODE>
__global__ __launch_bounds__(256, 2) void gemm_h(const float* __restrict__ bias,
                                                 float* __restrict__ Cout,
                                                 int K, int N)
{
    extern __shared__ uint32_t gsm[];
    const uint32_t smb = (uint32_t)__cvta_generic_to_shared(gsm);

    const int tid = threadIdx.x, wid = tid >> 5, lane = tid & 31;
    const int g = lane >> 2, t = lane & 3;
    const int wm = wid & 1, wn = wid >> 1;         // 2M x 4N warps
    const int m0 = blockIdx.x * 128, n0 = blockIdx.y * 128;

    const __half* __restrict__ Ap = (MODE == 1) ? g_yh : x_h;
    const __half* __restrict__ Wp = (MODE == 1) ? Wo_h : Wqkv_h;

    // ldmatrix lane offsets (bytes), row stride 144B
    const uint32_t aOff = (wm * 64 + (lane & 15)) * 144 + (lane >> 4) * 16;
    const uint32_t bOff = (wn * 32 + ((lane >> 4) & 1) * 8 + (lane & 7)) * 144
                        + ((lane >> 3) & 1) * 16;

    float4 acc[4][4];              // 4 m16-tiles x 4 n8-tiles
#pragma unroll
    for (int mt = 0; mt < 4; mt++)
#pragma unroll
        for (int j = 0; j < 4; j++) acc[mt][j] = make_float4(0.f, 0.f, 0.f, 0.f);

    const int nchunks = K / 64;   // 8
    auto issue = [&](int c, int s) {
        uint32_t base = smb + (uint32_t)s * GSTG_BYTES;
        // A: 128 rows x 8 uint4 = 1024; 4 per thread
#pragma unroll
        for (int it = 0; it < 4; it++) {
            int idx = tid + it * 256, row = idx >> 3, q = idx & 7;
            cp16(base + (uint32_t)(row * GLD + q * 4) * 4,
                 Ap + (size_t)(m0 + row) * K + c * 64 + q * 8);
        }
        // B: 128 rows x 8 uint4 = 1024; 4 per thread
#pragma unroll
        for (int it = 0; it < 4; it++) {
            int idx = tid + it * 256, row = idx >> 3, q = idx & 7;
            cp16(base + (uint32_t)GA_U32 * 4 + (uint32_t)(row * GLD + q * 4) * 4,
                 Wp + (size_t)(n0 + row) * K + c * 64 + q * 8);
        }
        CP_COMMIT();
    };

    issue(0, 0);
    for (int c = 0; c < nchunks; c++) {
        const int s = c & 1;
        CP_WAIT0();
        __syncthreads();
        if (c + 1 < nchunks) issue(c + 1, s ^ 1);

        const uint32_t aB = smb + (uint32_t)s * GSTG_BYTES + aOff;
        const uint32_t bB = smb + (uint32_t)s * GSTG_BYTES + (uint32_t)GA_U32 * 4 + bOff;
#pragma unroll
        for (int kc = 0; kc < 4; kc++) {
            uint32_t a[4][4], bf[4][2];
#pragma unroll
            for (int mt = 0; mt < 4; mt++)
                ldsm_x4(a[mt][0], a[mt][1], a[mt][2], a[mt][3],
                        aB + mt * 16 * 144 + kc * 32);
            ldsm_x4(bf[0][0], bf[0][1], bf[1][0], bf[1][1], bB + kc * 32);
            ldsm_x4(bf[2][0], bf[2][1], bf[3][0], bf[3][1], bB + 16 * 144 + kc * 32);
#pragma unroll
            for (int mt = 0; mt < 4; mt++)
#pragma unroll
                for (int j = 0; j < 4; j++)
                    mma_h(acc[mt][j], a[mt][0], a[mt][1], a[mt][2], a[mt][3],
                          bf[j][0], bf[j][1]);
        }
    }

    // Epilogue
#pragma unroll
    for (int j = 0; j < 4; j++) {
        int n = n0 + wn * 32 + j * 8 + 2 * t;
        float2 bb = *(const float2*)&bias[n];
#pragma unroll
        for (int mt = 0; mt < 4; mt++) {
            int ma = m0 + wm * 64 + mt * 16 + g;
            float x0 = acc[mt][j].x + bb.x, y0 = acc[mt][j].y + bb.y;
            float x1 = acc[mt][j].z + bb.x, y1 = acc[mt][j].w + bb.y;
            if (MODE == 0) {
                int sel = n >> 9, dd = n & 511, h = dd >> 6, hd0 = n & 63;
                __half* __restrict__ dst = (sel == 0) ? g_qh : ((sel == 1) ? g_kh : g_vh);
                int bh = (ma >> 12) * NH + h, s = ma & 4095;
                size_t base = ((size_t)bh * SEQ + s) * HD + hd0;
                *(uint32_t*)&dst[base] = h2u(__floats2half2_rn(x0, y0));
                *(uint32_t*)&dst[base + (size_t)8 * HD] = h2u(__floats2half2_rn(x1, y1));
            } else {
                *(float2*)&Cout[(size_t)ma * N + n] = make_float2(x0, y0);
                *(float2*)&Cout[(size_t)(ma + 8) * N + n] = make_float2(x1, y1);
            }
        }
    }
}

// ---------------------------------------------------------------------------
// Flash attention (R14-proven config): fp16 mma.sync, causal, no-max softmax,
// f16x2 exp, l-via-ones-MMA, V-frag pipeline, diagonal-only masking.
// 128 thr / 4 warps; Q tile 64 rows (16/warp); K tile 64 keys; 4 CTAs/SM
// (4 independent barrier domains per SM -- measured optimum).
// 3-stage cp.async K/V ring, one __syncthreads per k-tile.
// ---------------------------------------------------------------------------
#define SKV 36
#define KV_STG (2 * 64 * SKV)             // u32 per stage (K then V)
#define ATTN_DSM (3 * KV_STG * 4)         // 55,296 bytes

__global__ __launch_bounds__(128, 4) void attn_h()
{
    extern __shared__ uint32_t sm[];

    const int qt = (int)gridDim.x - 1 - (int)blockIdx.x;   // heavy blocks first
    const int bh = blockIdx.y;
    const int tid = threadIdx.x, wid = tid >> 5, lane = tid & 31;
    const int g = lane >> 2, t = lane & 3;
    const int q0 = qt * 64;
    const int r0 = q0 + wid * 16 + g;

    const __half* __restrict__ qb = g_qh + (size_t)bh * SEQ * HD;
    const __half* __restrict__ kb = g_kh + (size_t)bh * SEQ * HD;
    const __half* __restrict__ vb = g_vh + (size_t)bh * SEQ * HD;

    const uint32_t smb = (uint32_t)__cvta_generic_to_shared(sm);

    // cp.async staging: K,V each 512 uint4 over 128 thr = 4 each
    const int krb = tid >> 3, kq = tid & 7;
    const uint32_t kSoff = (uint32_t)(krb * SKV + kq * 4) * 4;
    const uint32_t vSoff = (uint32_t)(64 * SKV + krb * SKV + kq * 4) * 4;
    auto issue_kv = [&](int kt, int s) {
        uint32_t sb = smb + (uint32_t)s * (KV_STG * 4);
        const __half* ksrc = kb + (size_t)(kt * 64 + krb) * HD + kq * 8;
        const __half* vsrc = vb + (size_t)(kt * 64 + krb) * HD + kq * 8;
#pragma unroll
        for (int i = 0; i < 4; i++) {
            cp16(sb + kSoff + i * 16 * SKV * 4, ksrc + (size_t)i * 16 * HD);
            cp16(sb + vSoff + i * 16 * SKV * 4, vsrc + (size_t)i * 16 * HD);
        }
        CP_COMMIT();
    };

    // Q fragments in registers (constant over mainloop)
    uint32_t qf[4][4];
#pragma unroll
    for (int kc = 0; kc < 4; kc++) {
        qf[kc][0] = *(const uint32_t*)(qb + (size_t)r0 * HD + kc * 16 + 2 * t);
        qf[kc][1] = *(const uint32_t*)(qb + (size_t)(r0 + 8) * HD + kc * 16 + 2 * t);
        qf[kc][2] = *(const uint32_t*)(qb + (size_t)r0 * HD + kc * 16 + 8 + 2 * t);
        qf[kc][3] = *(const uint32_t*)(qb + (size_t)(r0 + 8) * HD + kc * 16 + 8 + 2 * t);
    }

    float4 o[8];
#pragma unroll
    for (int j = 0; j < 8; j++) o[j] = make_float4(0.f, 0.f, 0.f, 0.f);
    float4 lacc = make_float4(0.f, 0.f, 0.f, 0.f);   // l in .x (row g), .z (row g+8)
    const uint32_t ones_b = (g == 0) ? 0x3C003C00u : 0u;   // B[:,0]=1 fragment

    // ldmatrix lane offsets (bytes within a stage)
    const uint32_t kfOff = (((lane >> 4) << 3) + (lane & 7)) * (SKV * 4)
                         + ((lane >> 3) & 1) * 16;
    const uint32_t vfOff = (uint32_t)(64 * SKV * 4)
                         + (lane & 15) * (SKV * 4) + ((lane >> 4) & 1) * 16;

    issue_kv(0, 0);
    if (qt >= 1) issue_kv(1, 1);
    for (int kt = 0; kt <= qt; kt++) {
        const int s = kt % 3;
        if (kt < qt) CP_WAIT1();
        else         CP_WAIT0();
        __syncthreads();
        if (kt + 2 <= qt) issue_kv(kt + 2, (kt + 2) % 3);

        const uint32_t stg = smb + (uint32_t)s * (KV_STG * 4);
        const uint32_t kfBase = stg + kfOff;
        const uint32_t vfBase = stg + vfOff;

        // ---- preload V frags for kc=0 (independent of softmax) ----
        uint32_t vbuf[2][16];
#pragma unroll
        for (int jp = 0; jp < 4; jp++)
            ldsm_x4_trans(vbuf[0][4 * jp], vbuf[0][4 * jp + 1],
                          vbuf[0][4 * jp + 2], vbuf[0][4 * jp + 3],
                          vfBase + jp * 32);

        // ---- S = Q K^T (ldmatrix.x4 K frags) ----
        float4 sc[8];
#pragma unroll
        for (int j = 0; j < 8; j++) sc[j] = make_float4(0.f, 0.f, 0.f, 0.f);
#pragma unroll
        for (int kc = 0; kc < 4; kc++) {
            uint32_t base = kfBase + kc * 32;
#pragma unroll
            for (int jp = 0; jp < 4; jp++) {
                uint32_t b0, b1, b2, b3;
                ldsm_x4(b0, b1, b2, b3, base + jp * 16 * (SKV * 4));
                mma_h(sc[2 * jp],     qf[kc][0], qf[kc][1], qf[kc][2], qf[kc][3], b0, b1);
                mma_h(sc[2 * jp + 1], qf[kc][0], qf[kc][1], qf[kc][2], qf[kc][3], b2, b3);
            }
        }

        // ---- p = exp2(s*SC) in f16x2; mask only on the diagonal tile ----
        const float SC = 0.18033688f;   // 0.125 * log2(e)
        uint32_t pf[8][2];
        if (kt == qt) {                 // block-uniform branch
#pragma unroll
            for (int j = 0; j < 8; j++) {
                int c = kt * 64 + j * 8 + 2 * t;
                float vx = (c     > r0)     ? -64.f : sc[j].x * SC;
                float vy = (c + 1 > r0)     ? -64.f : sc[j].y * SC;
                float vz = (c     > r0 + 8) ? -64.f : sc[j].z * SC;
                float vw = (c + 1 > r0 + 8) ? -64.f : sc[j].w * SC;
                pf[j][0] = ex2_h2(h2u(__floats2half2_rn(vx, vy)));
                pf[j][1] = ex2_h2(h2u(__floats2half2_rn(vz, vw)));
            }
        } else {
#pragma unroll
            for (int j = 0; j < 8; j++) {
                pf[j][0] = ex2_h2(h2u(__floats2half2_rn(sc[j].x * SC, sc[j].y * SC)));
                pf[j][1] = ex2_h2(h2u(__floats2half2_rn(sc[j].z * SC, sc[j].w * SC)));
            }
        }

        // ---- O += P V ; l += P @ ones  (V-frag prefetch pipeline) ----
#pragma unroll
        for (int kc = 0; kc < 4; kc++) {
            if (kc < 3) {
                uint32_t nrow = vfBase + (uint32_t)(16 * (kc + 1)) * (SKV * 4);
#pragma unroll
                for (int jp = 0; jp < 4; jp++)
                    ldsm_x4_trans(vbuf[(kc + 1) & 1][4 * jp], vbuf[(kc + 1) & 1][4 * jp + 1],
                                  vbuf[(kc + 1) & 1][4 * jp + 2], vbuf[(kc + 1) & 1][4 * jp + 3],
                                  nrow + jp * 32);
            }
            uint32_t a0 = pf[2 * kc][0], a1 = pf[2 * kc][1];
            uint32_t a2 = pf[2 * kc + 1][0], a3 = pf[2 * kc + 1][1];
            mma_h(lacc, a0, a1, a2, a3, ones_b, ones_b);   // row-sum on tensor pipe
#pragma unroll
            for (int jp = 0; jp < 4; jp++) {
                mma_h(o[2 * jp],     a0, a1, a2, a3,
                      vbuf[kc & 1][4 * jp], vbuf[kc & 1][4 * jp + 1]);
                mma_h(o[2 * jp + 1], a0, a1, a2, a3,
                      vbuf[kc & 1][4 * jp + 2], vbuf[kc & 1][4 * jp + 3]);
            }
        }
    }

    // l lives in column 0 of lacc -> held by the t=0 lane of each quad
    const float l0 = __shfl_sync(0xffffffffu, lacc.x, lane & ~3);
    const float l1 = __shfl_sync(0xffffffffu, lacc.z, lane & ~3);

    // Write y as half [b][s][h*64+hd]
    const int b = bh >> 3, h = bh & 7;
    const float inv0 = 1.0f / l0, inv1 = 1.0f / l1;
    size_t base0 = ((size_t)b * SEQ + r0) * DMODEL + h * HD;
#pragma unroll
    for (int j = 0; j < 8; j++) {
        *(uint32_t*)&g_yh[base0 + j * 8 + 2 * t] =
            h2u(__floats2half2_rn(o[j].x * inv0, o[j].y * inv0));
        *(uint32_t*)&g_yh[base0 + (size_t)8 * DMODEL + j * 8 + 2 * t] =
            h2u(__floats2half2_rn(o[j].z * inv1, o[j].w * inv1));
    }
}

// ---------------------------------------------------------------------------
extern "C" void kernel_launch(void* const* d_in, const int* in_sizes, int n_in,
                              void* d_out, int out_size)
{
    const float* x    = (const float*)d_in[0];
    const float* Wqkv = (const float*)d_in[1];
    const float* bqkv = (const float*)d_in[2];
    const float* Wo   = (const float*)d_in[3];
    const float* bo   = (const float*)d_in[4];
    float* out = (float*)d_out;

    cudaFuncSetAttribute(gemm_h<0>,
                         cudaFuncAttributeMaxDynamicSharedMemorySize, GEMM_DSM);
    cudaFuncSetAttribute(gemm_h<1>,
                         cudaFuncAttributeMaxDynamicSharedMemorySize, GEMM_DSM);
    cudaFuncSetAttribute(attn_h,
                         cudaFuncAttributeMaxDynamicSharedMemorySize, ATTN_DSM);

    // 0) f32 -> f16 pre-conversion (single launch for x, Wqkv, Wo)
    f2h_all<<<((NX + NQ + NW) / 4 + 255) / 256, 256>>>(x, Wqkv, Wo);

    // 1) QKV projection (fp16 HMMA, 128x128 tile, chunk-64 2-stage ring)
    gemm_h<0><<<dim3(MTOT / 128, (3 * DMODEL) / 128), 256, GEMM_DSM>>>(
        bqkv, nullptr, DMODEL, 3 * DMODEL);

    // 2) Causal flash attention (R14 config: 64-row Q, 4 CTAs/SM)
    attn_h<<<dim3(SEQ / 64, BHT), 128, ATTN_DSM>>>();

    // 3) Output projection (fp16 HMMA, 128x128 tile)
    gemm_h<1><<<dim3(MTOT / 128, DMODEL / 128), 256, GEMM_DSM>>>(
        bo, out, DMODEL, DMODEL);
}